// round 16
// baseline (speedup 1.0000x reference)
#include <cuda_runtime.h>
#include <cuda_fp16.h>
#include <cstdint>

// selfAttention: N=2, L=2048, E=1024, H=16, D=64
// All-fp16 m16n8k16 mma (fp32 accum).
// R16: attention at 3 CTAs/SM (6 warps/SMSP) via register diet:
//  - mask words loaded post-barrier (latency hidden under QK), no prefetch regs
//  - softmax/PV fused per nt-pair (pa[2][2] instead of pa[8][2])
// Proj (512-thr, 8 warps/SMSP) + fused prep verbatim from R14 (201.2 us best).

#define NB    2
#define LSEQ  2048
#define EDIM  1024
#define NH    16
#define DH    64
#define QSC   0.18033688011112042f   /* 0.125 * log2(e) */
#define VSTRB 144                    /* smem row stride bytes (72 halves) */
#define AKBUF (64 * VSTRB)           /* one 64-key K/V tile buffer */
#define NT    (LSEQ / 64)
#define PBUF  (128 * VSTRB)          /* one proj tile buffer (A or W) */
#define PJ_SMEM (4 * PBUF)           /* 73728 B */

// ---------------- scratch ---------------------------------------------------
__device__ unsigned g_mbits[(size_t)NB * LSEQ * (LSEQ / 32)];   // 1 MB
__device__ __half   g_k16[(size_t)NB * LSEQ * EDIM];            // 8 MB
__device__ __half   g_v16[(size_t)NB * LSEQ * EDIM];            // 8 MB
__device__ __half   g_att16[(size_t)NB * LSEQ * EDIM];          // 8 MB
__device__ __half   g_w16[(size_t)EDIM * EDIM];                 // 2 MB

// ---------------- helpers ---------------------------------------------------
__device__ __forceinline__ uint32_t smem_u32(const void* p) {
    uint32_t a;
    asm("{ .reg .u64 t; cvta.to.shared.u64 t, %1; cvt.u32.u64 %0, t; }"
        : "=r"(a) : "l"(p));
    return a;
}
__device__ __forceinline__ float ex2f(float x) {
    float r; asm("ex2.approx.f32 %0, %1;" : "=f"(r) : "f"(x)); return r;
}
__device__ __forceinline__ uint32_t hpack(float a, float b) {
    __half2 h = __floats2half2_rn(a, b);   // a in low half
    return *(uint32_t*)&h;
}

#define MMAH(c, a, b0, b1) \
    asm volatile("mma.sync.aligned.m16n8k16.row.col.f32.f16.f16.f32 " \
        "{%0,%1,%2,%3}, {%4,%5,%6,%7}, {%8,%9}, {%0,%1,%2,%3};" \
        : "+f"((c)[0]), "+f"((c)[1]), "+f"((c)[2]), "+f"((c)[3]) \
        : "r"((a)[0]), "r"((a)[1]), "r"((a)[2]), "r"((a)[3]), \
          "r"(b0), "r"(b1))

#define LDSM4(r, ad) \
    asm volatile("ldmatrix.sync.aligned.m8n8.x4.shared.b16 {%0,%1,%2,%3}, [%4];" \
        : "=r"((r)[0]), "=r"((r)[1]), "=r"((r)[2]), "=r"((r)[3]) : "r"(ad))
#define LDSM4T(r, ad) \
    asm volatile("ldmatrix.sync.aligned.m8n8.x4.trans.shared.b16 {%0,%1,%2,%3}, [%4];" \
        : "=r"((r)[0]), "=r"((r)[1]), "=r"((r)[2]), "=r"((r)[3]) : "r"(ad))

#define CPA(dst, src) \
    asm volatile("cp.async.cg.shared.global [%0], [%1], 16;" \
        :: "r"((uint32_t)(dst)), "l"(__cvta_generic_to_global(src)) : "memory")
#define CPC()  asm volatile("cp.async.commit_group;" ::: "memory")
#define CPW0() asm volatile("cp.async.wait_group 0;" ::: "memory")
#define CPW1() asm volatile("cp.async.wait_group 1;" ::: "memory")

// ---------------- kernel 0: fused prologue (mask pack + fp16 convert) -------
__global__ void prep_kernel(const int* __restrict__ mask,
                            const float* __restrict__ K,
                            const float* __restrict__ V,
                            const float* __restrict__ W) {
    size_t t = (size_t)blockIdx.x * blockDim.x + threadIdx.x;
    float4 k4 = ((const float4*)K)[t];
    float4 v4 = ((const float4*)V)[t];
    ((uint2*)g_k16)[t] = make_uint2(hpack(k4.x, k4.y), hpack(k4.z, k4.w));
    ((uint2*)g_v16)[t] = make_uint2(hpack(v4.x, v4.y), hpack(v4.z, v4.w));
    if (t < (size_t)EDIM * EDIM / 4) {
        float4 w4 = ((const float4*)W)[t];
        ((uint2*)g_w16)[t] = make_uint2(hpack(w4.x, w4.y), hpack(w4.z, w4.w));
    }
    const int4* mp = (const int4*)mask + 2 * t;
    int4 a = mp[0], b = mp[1];
    unsigned byte =  (unsigned)(a.x != 0)       | ((unsigned)(a.y != 0) << 1)
                  | ((unsigned)(a.z != 0) << 2) | ((unsigned)(a.w != 0) << 3)
                  | ((unsigned)(b.x != 0) << 4) | ((unsigned)(b.y != 0) << 5)
                  | ((unsigned)(b.z != 0) << 6) | ((unsigned)(b.w != 0) << 7);
    unsigned v = byte << (8 * ((unsigned)t & 3));
    v |= __shfl_xor_sync(0xffffffffu, v, 1);
    v |= __shfl_xor_sync(0xffffffffu, v, 2);
    if ((t & 3) == 0) g_mbits[t >> 2] = v;
}

// ---------------- kernel 1: attention (3 CTAs/SM, fused softmax/PV) ---------
// grid (L/128=16, H=16, N=2), 256 thr (8 warps x 16 q-rows). 64-key tiles.
__global__ __launch_bounds__(256, 3) void attn_kernel(const float* __restrict__ Q)
{
    __shared__ __align__(16) char Ks[2 * AKBUF];
    __shared__ __align__(16) char Vs[2 * AKBUF];
    const uint32_t sbK = smem_u32(Ks), sbV = smem_u32(Vs);

    const int tid = threadIdx.x;
    const int wid = tid >> 5, lane = tid & 31;
    const int g = lane >> 2, tg = lane & 3;
    const int lrow = lane & 7, lgrp = lane >> 3;
    const int R0 = wid * 16 + g;
    const int n = blockIdx.z, h = blockIdx.y, q0 = blockIdx.x * 128;
    const size_t basehd = (size_t)n * LSEQ * EDIM + (size_t)h * DH;

    const int skey0 = tid >> 3, sseg = tid & 7;
    const __half* kgb = g_k16 + basehd + (size_t)sseg * 8;
    const __half* vgb = g_v16 + basehd + (size_t)sseg * 8;

    // ---- Q fragments from gmem (once), fp16 A-frag layout ----
    uint32_t qa[4][4];
    {
        const float* qp0 = Q + basehd + (size_t)(q0 + R0) * EDIM;
        const float* qp1 = qp0 + 8 * EDIM;
        #pragma unroll
        for (int s = 0; s < 4; s++) {
            float2 x0 = *(const float2*)(qp0 + 16 * s + 2 * tg);
            float2 x1 = *(const float2*)(qp1 + 16 * s + 2 * tg);
            float2 y0 = *(const float2*)(qp0 + 16 * s + 8 + 2 * tg);
            float2 y1 = *(const float2*)(qp1 + 16 * s + 8 + 2 * tg);
            qa[s][0] = hpack(x0.x, x0.y);
            qa[s][1] = hpack(x1.x, x1.y);
            qa[s][2] = hpack(y0.x, y0.y);
            qa[s][3] = hpack(y1.x, y1.y);
        }
    }
    const unsigned* Mb = g_mbits + ((size_t)(n * LSEQ) + q0) * (LSEQ / 32);

    float o[8][4];
    #pragma unroll
    for (int i = 0; i < 8; i++)
        #pragma unroll
        for (int j = 0; j < 4; j++) o[i][j] = 0.f;
    float lacc0 = 0.f, lacc1 = 0.f;

    // ---- prefetch tile 0 ----
    {
        uint32_t dk = sbK + skey0 * VSTRB + sseg * 16;
        uint32_t dv = sbV + skey0 * VSTRB + sseg * 16;
        CPA(dk,              kgb + (size_t)skey0 * EDIM);
        CPA(dk + 32 * VSTRB, kgb + (size_t)(skey0 + 32) * EDIM);
        CPA(dv,              vgb + (size_t)skey0 * EDIM);
        CPA(dv + 32 * VSTRB, vgb + (size_t)(skey0 + 32) * EDIM);
        CPC();
    }

    for (int kt = 0; kt < NT; kt++) {
        const int buf = kt & 1;
        if (kt + 1 < NT) {
            uint32_t dk = sbK + (buf ^ 1) * AKBUF + skey0 * VSTRB + sseg * 16;
            uint32_t dv = sbV + (buf ^ 1) * AKBUF + skey0 * VSTRB + sseg * 16;
            const __half* kg = kgb + (size_t)((kt + 1) * 64) * EDIM;
            const __half* vg = vgb + (size_t)((kt + 1) * 64) * EDIM;
            CPA(dk,              kg + (size_t)skey0 * EDIM);
            CPA(dk + 32 * VSTRB, kg + (size_t)(skey0 + 32) * EDIM);
            CPA(dv,              vg + (size_t)skey0 * EDIM);
            CPA(dv + 32 * VSTRB, vg + (size_t)(skey0 + 32) * EDIM);
            CPC();
            CPW1();
        } else {
            CPW0();
        }
        __syncthreads();

        // mask words for THIS tile: L2-hit LDG.64, consumed after ~4 MMA + LDSM
        // latency -> fully covered; no registers held across tiles.
        uint2 mra = *(const uint2*)(Mb + (size_t)R0 * 64 + kt * 2);
        uint2 mrb = *(const uint2*)(Mb + (size_t)(R0 + 8) * 64 + kt * 2);

        const uint32_t kbb = sbK + buf * AKBUF;
        const uint32_t vbb = sbV + buf * AKBUF;
        float lt0 = 0.f, lt1 = 0.f;

        // fused: per j, QK for nt-pair (2j, 2j+1) -> exp -> PV(j).
        // QK MMAs of pair j+1 are independent of PV MMAs of pair j (ILP).
        #pragma unroll
        for (int j = 0; j < 4; j++) {
            uint32_t pa[2][2];
            #pragma unroll
            for (int p = 0; p < 2; p++) {
                const int nt = 2 * j + p;
                float s4[4] = {0.f, 0.f, 0.f, 0.f};
                uint32_t kb = kbb + (8 * nt + lrow) * VSTRB + lgrp * 16;
                uint32_t bh[8];
                LDSM4(bh,     kb);
                LDSM4(bh + 4, kb + 64);
                MMAH(s4, qa[0], bh[0], bh[1]);
                MMAH(s4, qa[1], bh[2], bh[3]);
                MMAH(s4, qa[2], bh[4], bh[5]);
                MMAH(s4, qa[3], bh[6], bh[7]);

                unsigned w0 = (nt >> 2) ? mra.y : mra.x;
                unsigned w1 = (nt >> 2) ? mrb.y : mrb.x;
                int b = 8 * (nt & 3) + 2 * tg;
                float e0 = ((w0 >> b) & 1u)       ? ex2f(s4[0] * QSC) : 0.f;
                float e1 = ((w0 >> (b + 1)) & 1u) ? ex2f(s4[1] * QSC) : 0.f;
                float e2 = ((w1 >> b) & 1u)       ? ex2f(s4[2] * QSC) : 0.f;
                float e3 = ((w1 >> (b + 1)) & 1u) ? ex2f(s4[3] * QSC) : 0.f;
                lt0 += e0 + e1; lt1 += e2 + e3;
                pa[p][0] = hpack(e0, e1);
                pa[p][1] = hpack(e2, e3);
            }

            uint32_t ah[4] = { pa[0][0], pa[0][1], pa[1][0], pa[1][1] };
            uint32_t vrow = vbb + (j * 16 + lrow + (lgrp & 1) * 8) * VSTRB
                          + (lane >> 4) * 16;
            uint32_t vb[8];
            LDSM4T(vb,     vrow);
            LDSM4T(vb + 4, vrow + 32);
            MMAH(o[0], ah, vb[0], vb[1]);
            MMAH(o[1], ah, vb[2], vb[3]);
            MMAH(o[2], ah, vb[4], vb[5]);
            MMAH(o[3], ah, vb[6], vb[7]);
            LDSM4T(vb,     vrow + 64);
            LDSM4T(vb + 4, vrow + 96);
            MMAH(o[4], ah, vb[0], vb[1]);
            MMAH(o[5], ah, vb[2], vb[3]);
            MMAH(o[6], ah, vb[4], vb[5]);
            MMAH(o[7], ah, vb[6], vb[7]);
        }
        lacc0 += lt0; lacc1 += lt1;
        __syncthreads();   // all reads of buf done before it is re-staged
    }

    // ---- epilogue: quad-reduce denominators, normalize, store fp16 ----
    lacc0 += __shfl_xor_sync(0xffffffffu, lacc0, 1);
    lacc0 += __shfl_xor_sync(0xffffffffu, lacc0, 2);
    lacc1 += __shfl_xor_sync(0xffffffffu, lacc1, 1);
    lacc1 += __shfl_xor_sync(0xffffffffu, lacc1, 2);
    float inv0 = 1.f / lacc0, inv1 = 1.f / lacc1;

    uint32_t* ob = (uint32_t*)(g_att16 + ((size_t)(n * LSEQ) + q0) * EDIM + (size_t)h * DH);
    #pragma unroll
    for (int nt = 0; nt < 8; nt++) {
        int c = 8 * nt + 2 * tg;
        ob[((size_t)R0       * EDIM + c) >> 1] = hpack(o[nt][0] * inv0, o[nt][1] * inv0);
        ob[((size_t)(R0 + 8) * EDIM + c) >> 1] = hpack(o[nt][2] * inv1, o[nt][3] * inv1);
    }
}

// ---------------- kernel 2: projection (R14 verbatim) -----------------------
// out[4096x1024] = A @ W^T + b. 512 thr, 128x128 tiles, 8 warps/SMSP.
__global__ __launch_bounds__(512, 2) void proj_kernel(
    const float* __restrict__ bias, float* __restrict__ out)
{
    extern __shared__ __align__(16) char psm[];
    char* As = psm;
    char* Ws = psm + 2 * PBUF;
    const uint32_t sbA = smem_u32(As), sbW = smem_u32(Ws);

    const int tid = threadIdx.x;
    const int wid = tid >> 5, lane = tid & 31;
    const int g = lane >> 2, tg = lane & 3;
    const int lrow = lane & 7, lgrp = lane >> 3;
    const int rw = wid & 7, cw = wid >> 3;
    const int R0 = rw * 16 + g;
    const int col0 = blockIdx.x * 128, row0 = blockIdx.y * 128;

    const int sr = tid >> 2, sseg = tid & 3;
    const __half* agb = g_att16 + (size_t)(row0 + sr) * EDIM + sseg * 16;
    const __half* wgb = g_w16 + (size_t)(col0 + sr) * EDIM + sseg * 16;

    float acc[8][4];
    #pragma unroll
    for (int i = 0; i < 8; i++)
        #pragma unroll
        for (int j = 0; j < 4; j++) acc[i][j] = 0.f;

    CPA(sbA + sr * VSTRB + sseg * 32,      agb);
    CPA(sbA + sr * VSTRB + sseg * 32 + 16, agb + 8);
    CPA(sbW + sr * VSTRB + sseg * 32,      wgb);
    CPA(sbW + sr * VSTRB + sseg * 32 + 16, wgb + 8);
    CPC();

    for (int c = 0; c < EDIM / 64; c++) {
        const int buf = c & 1;
        if (c + 1 < EDIM / 64) {
            uint32_t bb = (buf ^ 1) * PBUF;
            CPA(sbA + bb + sr * VSTRB + sseg * 32,      agb + (c + 1) * 64);
            CPA(sbA + bb + sr * VSTRB + sseg * 32 + 16, agb + (c + 1) * 64 + 8);
            CPA(sbW + bb + sr * VSTRB + sseg * 32,      wgb + (c + 1) * 64);
            CPA(sbW + bb + sr * VSTRB + sseg * 32 + 16, wgb + (c + 1) * 64 + 8);
            CPC();
            CPW1();
        } else {
            CPW0();
        }
        __syncthreads();

        uint32_t aa[4][4];
        uint32_t abase = sbA + buf * PBUF + (rw * 16 + (lane & 15)) * VSTRB
                       + (lane >> 4) * 16;
        #pragma unroll
        for (int s = 0; s < 4; s++) LDSM4(aa[s], abase + s * 32);

        #pragma unroll
        for (int nt = 0; nt < 8; nt++) {
            uint32_t kb = sbW + buf * PBUF + (cw * 64 + 8 * nt + lrow) * VSTRB
                        + lgrp * 16;
            uint32_t b0[4], b1[4];
            LDSM4(b0, kb);
            LDSM4(b1, kb + 64);
            MMAH(acc[nt], aa[0], b0[0], b0[1]);
            MMAH(acc[nt], aa[1], b0[2], b0[3]);
            MMAH(acc[nt], aa[2], b1[0], b1[1]);
            MMAH(acc[nt], aa[3], b1[2], b1[3]);
        }
        __syncthreads();
    }

    float* op0 = out + (size_t)(row0 + R0) * EDIM + col0 + cw * 64;
    float* op1 = op0 + 8 * EDIM;
    #pragma unroll
    for (int nt = 0; nt < 8; nt++) {
        int cc = 8 * nt + 2 * tg;
        float2 b2 = *(const float2*)(bias + col0 + cw * 64 + cc);
        *(float2*)(op0 + cc) = make_float2(acc[nt][0] + b2.x, acc[nt][1] + b2.y);
        *(float2*)(op1 + cc) = make_float2(acc[nt][2] + b2.x, acc[nt][3] + b2.y);
    }
}

// ---------------------------------------------------------------------------
extern "C" void kernel_launch(void* const* d_in, const int* in_sizes, int n_in,
                              void* d_out, int out_size) {
    const float* Vv = (const float*)d_in[0];
    const float* Kk = (const float*)d_in[1];
    const float* Qq = (const float*)d_in[2];
    const int*   Mm = (const int*)d_in[3];
    const float* Wo = (const float*)d_in[4];
    const float* bo = (const float*)d_in[5];
    float* out = (float*)d_out;

    cudaFuncSetAttribute(proj_kernel,
                         cudaFuncAttributeMaxDynamicSharedMemorySize, PJ_SMEM);

    prep_kernel<<<((size_t)NB * LSEQ * EDIM / 4) / 256, 256>>>(Mm, Kk, Vv, Wo);
    attn_kernel<<<dim3(LSEQ / 128, NH, NB), 256>>>(Qq);
    proj_kernel<<<dim3(EDIM / 128, (NB * LSEQ) / 128), 512, PJ_SMEM>>>(bo, out);
}

// round 17
// speedup vs baseline: 1.1068x; 1.1068x over previous
#include <cuda_runtime.h>
#include <cuda_fp16.h>
#include <cstdint>

// selfAttention: N=2, L=2048, E=1024, H=16, D=64
// All-fp16 m16n8k16 mma (fp32 accum).
// R17 = R14 (201.2 us best) with ONE mechanical change: single-barrier
// pipelined loops (CPW -> sync -> CPA(next) -> compute) in both attention
// and projection. Halves __syncthreads count; zero math/register changes.

#define NB    2
#define LSEQ  2048
#define EDIM  1024
#define NH    16
#define DH    64
#define QSC   0.18033688011112042f   /* 0.125 * log2(e) */
#define VSTRB 144                    /* smem row stride bytes (72 halves) */
#define AKBUF (64 * VSTRB)           /* one 64-key K/V tile buffer */
#define NT    (LSEQ / 64)
#define PBUF  (128 * VSTRB)          /* one proj tile buffer (A or W) */
#define PJ_SMEM (4 * PBUF)           /* 73728 B */

// ---------------- scratch ---------------------------------------------------
__device__ unsigned g_mbits[(size_t)NB * LSEQ * (LSEQ / 32)];   // 1 MB
__device__ __half   g_k16[(size_t)NB * LSEQ * EDIM];            // 8 MB
__device__ __half   g_v16[(size_t)NB * LSEQ * EDIM];            // 8 MB
__device__ __half   g_att16[(size_t)NB * LSEQ * EDIM];          // 8 MB
__device__ __half   g_w16[(size_t)EDIM * EDIM];                 // 2 MB

// ---------------- helpers ---------------------------------------------------
__device__ __forceinline__ uint32_t smem_u32(const void* p) {
    uint32_t a;
    asm("{ .reg .u64 t; cvta.to.shared.u64 t, %1; cvt.u32.u64 %0, t; }"
        : "=r"(a) : "l"(p));
    return a;
}
__device__ __forceinline__ float ex2f(float x) {
    float r; asm("ex2.approx.f32 %0, %1;" : "=f"(r) : "f"(x)); return r;
}
__device__ __forceinline__ uint32_t hpack(float a, float b) {
    __half2 h = __floats2half2_rn(a, b);   // a in low half
    return *(uint32_t*)&h;
}

#define MMAH(c, a, b0, b1) \
    asm volatile("mma.sync.aligned.m16n8k16.row.col.f32.f16.f16.f32 " \
        "{%0,%1,%2,%3}, {%4,%5,%6,%7}, {%8,%9}, {%0,%1,%2,%3};" \
        : "+f"((c)[0]), "+f"((c)[1]), "+f"((c)[2]), "+f"((c)[3]) \
        : "r"((a)[0]), "r"((a)[1]), "r"((a)[2]), "r"((a)[3]), \
          "r"(b0), "r"(b1))

#define LDSM4(r, ad) \
    asm volatile("ldmatrix.sync.aligned.m8n8.x4.shared.b16 {%0,%1,%2,%3}, [%4];" \
        : "=r"((r)[0]), "=r"((r)[1]), "=r"((r)[2]), "=r"((r)[3]) : "r"(ad))
#define LDSM4T(r, ad) \
    asm volatile("ldmatrix.sync.aligned.m8n8.x4.trans.shared.b16 {%0,%1,%2,%3}, [%4];" \
        : "=r"((r)[0]), "=r"((r)[1]), "=r"((r)[2]), "=r"((r)[3]) : "r"(ad))

#define CPA(dst, src) \
    asm volatile("cp.async.cg.shared.global [%0], [%1], 16;" \
        :: "r"((uint32_t)(dst)), "l"(__cvta_generic_to_global(src)) : "memory")
#define CPC()  asm volatile("cp.async.commit_group;" ::: "memory")
#define CPW0() asm volatile("cp.async.wait_group 0;" ::: "memory")

// ---------------- kernel 0: fused prologue (mask pack + fp16 convert) -------
__global__ void prep_kernel(const int* __restrict__ mask,
                            const float* __restrict__ K,
                            const float* __restrict__ V,
                            const float* __restrict__ W) {
    size_t t = (size_t)blockIdx.x * blockDim.x + threadIdx.x;
    float4 k4 = ((const float4*)K)[t];
    float4 v4 = ((const float4*)V)[t];
    ((uint2*)g_k16)[t] = make_uint2(hpack(k4.x, k4.y), hpack(k4.z, k4.w));
    ((uint2*)g_v16)[t] = make_uint2(hpack(v4.x, v4.y), hpack(v4.z, v4.w));
    if (t < (size_t)EDIM * EDIM / 4) {
        float4 w4 = ((const float4*)W)[t];
        ((uint2*)g_w16)[t] = make_uint2(hpack(w4.x, w4.y), hpack(w4.z, w4.w));
    }
    const int4* mp = (const int4*)mask + 2 * t;
    int4 a = mp[0], b = mp[1];
    unsigned byte =  (unsigned)(a.x != 0)       | ((unsigned)(a.y != 0) << 1)
                  | ((unsigned)(a.z != 0) << 2) | ((unsigned)(a.w != 0) << 3)
                  | ((unsigned)(b.x != 0) << 4) | ((unsigned)(b.y != 0) << 5)
                  | ((unsigned)(b.z != 0) << 6) | ((unsigned)(b.w != 0) << 7);
    unsigned v = byte << (8 * ((unsigned)t & 3));
    v |= __shfl_xor_sync(0xffffffffu, v, 1);
    v |= __shfl_xor_sync(0xffffffffu, v, 2);
    if ((t & 3) == 0) g_mbits[t >> 2] = v;
}

// ---------------- kernel 1: attention (R14 + single-barrier loop) -----------
// grid (L/128=16, H=16, N=2), 256 thr (8 warps x 16 q-rows). 64-key tiles.
__global__ __launch_bounds__(256, 2) void attn_kernel(const float* __restrict__ Q)
{
    __shared__ __align__(16) char Ks[2 * AKBUF];
    __shared__ __align__(16) char Vs[2 * AKBUF];
    const uint32_t sbK = smem_u32(Ks), sbV = smem_u32(Vs);

    const int tid = threadIdx.x;
    const int wid = tid >> 5, lane = tid & 31;
    const int g = lane >> 2, tg = lane & 3;
    const int lrow = lane & 7, lgrp = lane >> 3;
    const int R0 = wid * 16 + g;
    const int n = blockIdx.z, h = blockIdx.y, q0 = blockIdx.x * 128;
    const size_t basehd = (size_t)n * LSEQ * EDIM + (size_t)h * DH;

    const int skey0 = tid >> 3, sseg = tid & 7;
    const __half* kgb = g_k16 + basehd + (size_t)sseg * 8;
    const __half* vgb = g_v16 + basehd + (size_t)sseg * 8;

    // ---- Q fragments from gmem (once), fp16 A-frag layout ----
    uint32_t qa[4][4];
    {
        const float* qp0 = Q + basehd + (size_t)(q0 + R0) * EDIM;
        const float* qp1 = qp0 + 8 * EDIM;
        #pragma unroll
        for (int s = 0; s < 4; s++) {
            float2 x0 = *(const float2*)(qp0 + 16 * s + 2 * tg);
            float2 x1 = *(const float2*)(qp1 + 16 * s + 2 * tg);
            float2 y0 = *(const float2*)(qp0 + 16 * s + 8 + 2 * tg);
            float2 y1 = *(const float2*)(qp1 + 16 * s + 8 + 2 * tg);
            qa[s][0] = hpack(x0.x, x0.y);
            qa[s][1] = hpack(x1.x, x1.y);
            qa[s][2] = hpack(y0.x, y0.y);
            qa[s][3] = hpack(y1.x, y1.y);
        }
    }
    const unsigned* Mb = g_mbits + ((size_t)(n * LSEQ) + q0) * (LSEQ / 32);

    float o[8][4];
    #pragma unroll
    for (int i = 0; i < 8; i++)
        #pragma unroll
        for (int j = 0; j < 4; j++) o[i][j] = 0.f;
    float lacc0 = 0.f, lacc1 = 0.f;

    // ---- prefetch tile 0 + its mask words ----
    {
        uint32_t dk = sbK + skey0 * VSTRB + sseg * 16;
        uint32_t dv = sbV + skey0 * VSTRB + sseg * 16;
        CPA(dk,              kgb + (size_t)skey0 * EDIM);
        CPA(dk + 32 * VSTRB, kgb + (size_t)(skey0 + 32) * EDIM);
        CPA(dv,              vgb + (size_t)skey0 * EDIM);
        CPA(dv + 32 * VSTRB, vgb + (size_t)(skey0 + 32) * EDIM);
        CPC();
    }
    uint2 mra = *(const uint2*)(Mb + (size_t)R0 * 64);
    uint2 mrb = *(const uint2*)(Mb + (size_t)(R0 + 8) * 64);

    for (int kt = 0; kt < NT; kt++) {
        const int buf = kt & 1;

        // single barrier: group(kt) complete AND all reads of buf^1 (done in
        // iteration kt-1) finished -> safe to re-stage buf^1 below.
        CPW0();
        __syncthreads();

        uint2 nma, nmb;
        if (kt + 1 < NT) {
            uint32_t dk = sbK + (buf ^ 1) * AKBUF + skey0 * VSTRB + sseg * 16;
            uint32_t dv = sbV + (buf ^ 1) * AKBUF + skey0 * VSTRB + sseg * 16;
            const __half* kg = kgb + (size_t)((kt + 1) * 64) * EDIM;
            const __half* vg = vgb + (size_t)((kt + 1) * 64) * EDIM;
            CPA(dk,              kg + (size_t)skey0 * EDIM);
            CPA(dk + 32 * VSTRB, kg + (size_t)(skey0 + 32) * EDIM);
            CPA(dv,              vg + (size_t)skey0 * EDIM);
            CPA(dv + 32 * VSTRB, vg + (size_t)(skey0 + 32) * EDIM);
            CPC();
            nma = *(const uint2*)(Mb + (size_t)R0 * 64 + (kt + 1) * 2);
            nmb = *(const uint2*)(Mb + (size_t)(R0 + 8) * 64 + (kt + 1) * 2);
        }

        const uint32_t kbb = sbK + buf * AKBUF;
        const uint32_t vbb = sbV + buf * AKBUF;
        uint32_t pa[8][2];
        float lt0 = 0.f, lt1 = 0.f;
        #pragma unroll
        for (int nt = 0; nt < 8; nt++) {
            float s4[4] = {0.f, 0.f, 0.f, 0.f};
            uint32_t kb = kbb + (8 * nt + lrow) * VSTRB + lgrp * 16;
            uint32_t bh[8];
            LDSM4(bh,     kb);
            LDSM4(bh + 4, kb + 64);
            MMAH(s4, qa[0], bh[0], bh[1]);
            MMAH(s4, qa[1], bh[2], bh[3]);
            MMAH(s4, qa[2], bh[4], bh[5]);
            MMAH(s4, qa[3], bh[6], bh[7]);

            unsigned w0 = (nt >> 2) ? mra.y : mra.x;
            unsigned w1 = (nt >> 2) ? mrb.y : mrb.x;
            int b = 8 * (nt & 3) + 2 * tg;
            float e0 = ((w0 >> b) & 1u)       ? ex2f(s4[0] * QSC) : 0.f;
            float e1 = ((w0 >> (b + 1)) & 1u) ? ex2f(s4[1] * QSC) : 0.f;
            float e2 = ((w1 >> b) & 1u)       ? ex2f(s4[2] * QSC) : 0.f;
            float e3 = ((w1 >> (b + 1)) & 1u) ? ex2f(s4[3] * QSC) : 0.f;
            lt0 += e0 + e1; lt1 += e2 + e3;
            pa[nt][0] = hpack(e0, e1);
            pa[nt][1] = hpack(e2, e3);
        }
        lacc0 += lt0; lacc1 += lt1;

        #pragma unroll
        for (int j = 0; j < 4; j++) {
            uint32_t ah[4] = { pa[2*j][0], pa[2*j][1], pa[2*j+1][0], pa[2*j+1][1] };
            uint32_t vrow = vbb + (j * 16 + lrow + (lgrp & 1) * 8) * VSTRB
                          + (lane >> 4) * 16;
            uint32_t vb[16];
            #pragma unroll
            for (int dp = 0; dp < 4; dp++) LDSM4T(vb + 4 * dp, vrow + dp * 32);
            #pragma unroll
            for (int nt = 0; nt < 8; nt++) MMAH(o[nt], ah, vb[2*nt], vb[2*nt+1]);
        }

        mra = nma; mrb = nmb;
    }

    // ---- epilogue (no smem use -> no barrier needed) ----
    lacc0 += __shfl_xor_sync(0xffffffffu, lacc0, 1);
    lacc0 += __shfl_xor_sync(0xffffffffu, lacc0, 2);
    lacc1 += __shfl_xor_sync(0xffffffffu, lacc1, 1);
    lacc1 += __shfl_xor_sync(0xffffffffu, lacc1, 2);
    float inv0 = 1.f / lacc0, inv1 = 1.f / lacc1;

    uint32_t* ob = (uint32_t*)(g_att16 + ((size_t)(n * LSEQ) + q0) * EDIM + (size_t)h * DH);
    #pragma unroll
    for (int nt = 0; nt < 8; nt++) {
        int c = 8 * nt + 2 * tg;
        ob[((size_t)R0       * EDIM + c) >> 1] = hpack(o[nt][0] * inv0, o[nt][1] * inv0);
        ob[((size_t)(R0 + 8) * EDIM + c) >> 1] = hpack(o[nt][2] * inv1, o[nt][3] * inv1);
    }
}

// ---------------- kernel 2: projection (R14 + single-barrier loop) ----------
// out[4096x1024] = A @ W^T + b. 512 thr, 128x128 tiles, 8 warps/SMSP.
__global__ __launch_bounds__(512, 2) void proj_kernel(
    const float* __restrict__ bias, float* __restrict__ out)
{
    extern __shared__ __align__(16) char psm[];
    char* As = psm;
    char* Ws = psm + 2 * PBUF;
    const uint32_t sbA = smem_u32(As), sbW = smem_u32(Ws);

    const int tid = threadIdx.x;
    const int wid = tid >> 5, lane = tid & 31;
    const int g = lane >> 2, tg = lane & 3;
    const int lrow = lane & 7, lgrp = lane >> 3;
    const int rw = wid & 7, cw = wid >> 3;
    const int R0 = rw * 16 + g;
    const int col0 = blockIdx.x * 128, row0 = blockIdx.y * 128;

    const int sr = tid >> 2, sseg = tid & 3;
    const __half* agb = g_att16 + (size_t)(row0 + sr) * EDIM + sseg * 16;
    const __half* wgb = g_w16 + (size_t)(col0 + sr) * EDIM + sseg * 16;

    float acc[8][4];
    #pragma unroll
    for (int i = 0; i < 8; i++)
        #pragma unroll
        for (int j = 0; j < 4; j++) acc[i][j] = 0.f;

    CPA(sbA + sr * VSTRB + sseg * 32,      agb);
    CPA(sbA + sr * VSTRB + sseg * 32 + 16, agb + 8);
    CPA(sbW + sr * VSTRB + sseg * 32,      wgb);
    CPA(sbW + sr * VSTRB + sseg * 32 + 16, wgb + 8);
    CPC();

    for (int c = 0; c < EDIM / 64; c++) {
        const int buf = c & 1;

        // single barrier: group(c) complete AND reads of buf^1 (iter c-1) done.
        CPW0();
        __syncthreads();

        if (c + 1 < EDIM / 64) {
            uint32_t bb = (buf ^ 1) * PBUF;
            CPA(sbA + bb + sr * VSTRB + sseg * 32,      agb + (c + 1) * 64);
            CPA(sbA + bb + sr * VSTRB + sseg * 32 + 16, agb + (c + 1) * 64 + 8);
            CPA(sbW + bb + sr * VSTRB + sseg * 32,      wgb + (c + 1) * 64);
            CPA(sbW + bb + sr * VSTRB + sseg * 32 + 16, wgb + (c + 1) * 64 + 8);
            CPC();
        }

        uint32_t aa[4][4];
        uint32_t abase = sbA + buf * PBUF + (rw * 16 + (lane & 15)) * VSTRB
                       + (lane >> 4) * 16;
        #pragma unroll
        for (int s = 0; s < 4; s++) LDSM4(aa[s], abase + s * 32);

        #pragma unroll
        for (int nt = 0; nt < 8; nt++) {
            uint32_t kb = sbW + buf * PBUF + (cw * 64 + 8 * nt + lrow) * VSTRB
                        + lgrp * 16;
            uint32_t b0[4], b1[4];
            LDSM4(b0, kb);
            LDSM4(b1, kb + 64);
            MMAH(acc[nt], aa[0], b0[0], b0[1]);
            MMAH(acc[nt], aa[1], b0[2], b0[3]);
            MMAH(acc[nt], aa[2], b1[0], b1[1]);
            MMAH(acc[nt], aa[3], b1[2], b1[3]);
        }
    }

    float* op0 = out + (size_t)(row0 + R0) * EDIM + col0 + cw * 64;
    float* op1 = op0 + 8 * EDIM;
    #pragma unroll
    for (int nt = 0; nt < 8; nt++) {
        int cc = 8 * nt + 2 * tg;
        float2 b2 = *(const float2*)(bias + col0 + cw * 64 + cc);
        *(float2*)(op0 + cc) = make_float2(acc[nt][0] + b2.x, acc[nt][1] + b2.y);
        *(float2*)(op1 + cc) = make_float2(acc[nt][2] + b2.x, acc[nt][3] + b2.y);
    }
}

// ---------------------------------------------------------------------------
extern "C" void kernel_launch(void* const* d_in, const int* in_sizes, int n_in,
                              void* d_out, int out_size) {
    const float* Vv = (const float*)d_in[0];
    const float* Kk = (const float*)d_in[1];
    const float* Qq = (const float*)d_in[2];
    const int*   Mm = (const int*)d_in[3];
    const float* Wo = (const float*)d_in[4];
    const float* bo = (const float*)d_in[5];
    float* out = (float*)d_out;

    cudaFuncSetAttribute(proj_kernel,
                         cudaFuncAttributeMaxDynamicSharedMemorySize, PJ_SMEM);

    prep_kernel<<<((size_t)NB * LSEQ * EDIM / 4) / 256, 256>>>(Mm, Kk, Vv, Wo);
    attn_kernel<<<dim3(LSEQ / 128, NH, NB), 256>>>(Qq);
    proj_kernel<<<dim3(EDIM / 128, (NB * LSEQ) / 128), 512, PJ_SMEM>>>(bo, out);
}